// round 2
// baseline (speedup 1.0000x reference)
#include <cuda_runtime.h>
#include <cuda_bf16.h>
#include <math.h>

// Problem constants
#define BATCH 32
#define SEQ   2048
#define DIM   1024
#define MROWS (BATCH * SEQ)   // 65536

// GEMM tiling
#define BM 128
#define BN 128
#define BK 16

// Scratch (no cudaMalloc allowed)
__device__ float g_qproj[BATCH * DIM];     // 128 KB
__device__ float g_score[BATCH * SEQ];     // 256 KB

// ---------------------------------------------------------------------------
// Kernel 1: q_proj[b,e] = dot(query[b,:], W1[e,:]) + W1_b[e]
// one warp per output element, vectorized float4 loads
// ---------------------------------------------------------------------------
__global__ void qproj_kernel(const float* __restrict__ q,
                             const float* __restrict__ W1,
                             const float* __restrict__ W1b,
                             float* __restrict__ qout) {
    int gw   = (blockIdx.x * blockDim.x + threadIdx.x) >> 5;
    int lane = threadIdx.x & 31;
    if (gw >= BATCH * DIM) return;
    int b = gw >> 10;
    int e = gw & 1023;
    const float4* qr = (const float4*)(q  + (size_t)b * DIM);
    const float4* wr = (const float4*)(W1 + (size_t)e * DIM);
    float acc = 0.f;
#pragma unroll
    for (int i = 0; i < 8; ++i) {
        float4 a = qr[lane + i * 32];
        float4 w = wr[lane + i * 32];
        acc += a.x * w.x + a.y * w.y + a.z * w.z + a.w * w.w;
    }
#pragma unroll
    for (int off = 16; off; off >>= 1)
        acc += __shfl_down_sync(0xffffffffu, acc, off);
    if (lane == 0) qout[gw] = acc + W1b[e];
}

// ---------------------------------------------------------------------------
// Kernel 2 (dominant): fused score GEMM.
//   score[r] = V_b + sum_n Vw[n] * tanh( key[r,:]*W2[n,:] + W2b[n] + qproj[b,n] )
// 128x128 output tile, BK=16, double-buffered smem, 8x8 per-thread microtile.
// Epilogue fuses tanh + V-dot + half-warp reduce -> smem accumulator.
// ---------------------------------------------------------------------------
__global__ __launch_bounds__(256, 2)
void score_kernel(const float* __restrict__ key,
                  const float* __restrict__ W2,
                  const float* __restrict__ W2b,
                  const float* __restrict__ qproj,
                  const float* __restrict__ Vw,
                  const float* __restrict__ Vb_p,
                  float* __restrict__ score_g) {
    __shared__ __align__(16) float As[2][BK][BM];
    __shared__ __align__(16) float Bs[2][BK][BN];
    __shared__ __align__(16) float qsm[DIM];   // qproj[b,:] + W2b[:]
    __shared__ __align__(16) float vsm[DIM];   // Vw
    __shared__ float score_sm[BM];

    const int tid  = threadIdx.x;
    const int row0 = blockIdx.x * BM;          // aligned within one batch (2048%128==0)
    const int b    = row0 >> 11;               // /2048

    for (int i = tid; i < DIM; i += 256) {
        qsm[i] = qproj[b * DIM + i] + W2b[i];
        vsm[i] = Vw[i];
    }
    if (tid < BM) score_sm[tid] = 0.f;

    const int ty = tid >> 4;   // 0..15 -> row group
    const int tx = tid & 15;   // 0..15 -> col group
    const float* keyA = key + (size_t)row0 * DIM;

    for (int nt = 0; nt < DIM / BN; ++nt) {
        const float* Wb = W2 + (size_t)(nt * BN) * DIM;

        float acc[8][8];
#pragma unroll
        for (int i = 0; i < 8; ++i)
#pragma unroll
            for (int j = 0; j < 8; ++j) acc[i][j] = 0.f;

        __syncthreads();   // guard smem tile reuse across nt iterations

        // preload k-tile 0 into buffer 0
#pragma unroll
        for (int l = 0; l < 2; ++l) {
            int idx = tid + l * 256;       // 0..511
            int m   = idx >> 2;            // 0..127
            int k4  = (idx & 3) * 4;       // 0,4,8,12
            float4 av = *(const float4*)(keyA + (size_t)m * DIM + k4);
            float4 bv = *(const float4*)(Wb   + (size_t)m * DIM + k4);
            As[0][k4 + 0][m] = av.x; As[0][k4 + 1][m] = av.y;
            As[0][k4 + 2][m] = av.z; As[0][k4 + 3][m] = av.w;
            Bs[0][k4 + 0][m] = bv.x; Bs[0][k4 + 1][m] = bv.y;
            Bs[0][k4 + 2][m] = bv.z; Bs[0][k4 + 3][m] = bv.w;
        }
        __syncthreads();

        int cur = 0;
        for (int kt = 0; kt < DIM; kt += BK) {
            const bool more = (kt + BK) < DIM;
            float4 pa[2], pb[2];
            if (more) {
#pragma unroll
                for (int l = 0; l < 2; ++l) {
                    int idx = tid + l * 256;
                    int m   = idx >> 2;
                    int k4  = (idx & 3) * 4;
                    pa[l] = *(const float4*)(keyA + (size_t)m * DIM + kt + BK + k4);
                    pb[l] = *(const float4*)(Wb   + (size_t)m * DIM + kt + BK + k4);
                }
            }
#pragma unroll
            for (int k = 0; k < BK; ++k) {
                float a[8], bb[8];
                *(float4*)&a[0]  = *(const float4*)&As[cur][k][ty * 8];
                *(float4*)&a[4]  = *(const float4*)&As[cur][k][ty * 8 + 4];
                *(float4*)&bb[0] = *(const float4*)&Bs[cur][k][tx * 8];
                *(float4*)&bb[4] = *(const float4*)&Bs[cur][k][tx * 8 + 4];
#pragma unroll
                for (int i = 0; i < 8; ++i)
#pragma unroll
                    for (int j = 0; j < 8; ++j)
                        acc[i][j] = fmaf(a[i], bb[j], acc[i][j]);
            }
            if (more) {
#pragma unroll
                for (int l = 0; l < 2; ++l) {
                    int idx = tid + l * 256;
                    int m   = idx >> 2;
                    int k4  = (idx & 3) * 4;
                    As[cur ^ 1][k4 + 0][m] = pa[l].x; As[cur ^ 1][k4 + 1][m] = pa[l].y;
                    As[cur ^ 1][k4 + 2][m] = pa[l].z; As[cur ^ 1][k4 + 3][m] = pa[l].w;
                    Bs[cur ^ 1][k4 + 0][m] = pb[l].x; Bs[cur ^ 1][k4 + 1][m] = pb[l].y;
                    Bs[cur ^ 1][k4 + 2][m] = pb[l].z; Bs[cur ^ 1][k4 + 3][m] = pb[l].w;
                }
                __syncthreads();
                cur ^= 1;
            }
        }

        // fused epilogue: tanh + dot with V, reduce over the 16 col-threads
#pragma unroll
        for (int i = 0; i < 8; ++i) {
            float s = 0.f;
#pragma unroll
            for (int j = 0; j < 8; ++j) {
                int n = nt * BN + tx * 8 + j;
                s += tanhf(acc[i][j] + qsm[n]) * vsm[n];
            }
#pragma unroll
            for (int off = 8; off; off >>= 1)
                s += __shfl_down_sync(0xffffffffu, s, off, 16);
            if (tx == 0) atomicAdd(&score_sm[ty * 8 + i], s);
        }
    }

    __syncthreads();
    if (tid < BM) score_g[row0 + tid] = score_sm[tid] + Vb_p[0];
}

// ---------------------------------------------------------------------------
// Kernel 3: softmax over S per batch row. One block per batch.
// ---------------------------------------------------------------------------
__global__ void softmax_kernel(const float* __restrict__ score,
                               float* __restrict__ attn) {
    const int b   = blockIdx.x;
    const int tid = threadIdx.x;   // 256
    __shared__ float red[256];
    const float* sr = score + (size_t)b * SEQ;

    float v[8];
    float mx = -INFINITY;
#pragma unroll
    for (int i = 0; i < 8; ++i) {
        v[i] = sr[tid + i * 256];
        mx = fmaxf(mx, v[i]);
    }
    red[tid] = mx;
    __syncthreads();
    for (int s = 128; s; s >>= 1) {
        if (tid < s) red[tid] = fmaxf(red[tid], red[tid + s]);
        __syncthreads();
    }
    const float m = red[0];
    __syncthreads();

    float sum = 0.f;
#pragma unroll
    for (int i = 0; i < 8; ++i) {
        v[i] = expf(v[i] - m);
        sum += v[i];
    }
    red[tid] = sum;
    __syncthreads();
    for (int s = 128; s; s >>= 1) {
        if (tid < s) red[tid] += red[tid + s];
        __syncthreads();
    }
    const float inv = 1.f / red[0];
#pragma unroll
    for (int i = 0; i < 8; ++i)
        attn[(size_t)b * SEQ + tid + i * 256] = v[i] * inv;
}

// ---------------------------------------------------------------------------
// Kernel 4a: zero the context region of d_out (it is poisoned to 0xAA)
// ---------------------------------------------------------------------------
__global__ void zero_ctx_kernel(float* __restrict__ ctx) {
    ctx[(size_t)blockIdx.x * 1024 + threadIdx.x] = 0.f;
}

// ---------------------------------------------------------------------------
// Kernel 4b: context[b,d] += sum_{s in chunk} attn[b,s] * value[b,s,d]
// grid (B, D/256, 4 s-chunks), atomicAdd for the s-split (MLP for HBM).
// ---------------------------------------------------------------------------
__global__ void context_kernel(const float* __restrict__ attn,
                               const float* __restrict__ value,
                               float* __restrict__ ctx) {
    const int b  = blockIdx.x;
    const int d  = blockIdx.y * 256 + threadIdx.x;
    const int s0 = blockIdx.z * (SEQ / 4);
    const float* vp = value + ((size_t)b * SEQ + s0) * DIM + d;
    const float* ap = attn + (size_t)b * SEQ + s0;
    float acc = 0.f;
#pragma unroll 8
    for (int s = 0; s < SEQ / 4; ++s)
        acc = fmaf(__ldg(ap + s), vp[(size_t)s * DIM], acc);
    atomicAdd(&ctx[(size_t)b * DIM + d], acc);
}

// ---------------------------------------------------------------------------
extern "C" void kernel_launch(void* const* d_in, const int* in_sizes, int n_in,
                              void* d_out, int out_size) {
    const float* query = (const float*)d_in[0];
    const float* key   = (const float*)d_in[1];
    const float* value = (const float*)d_in[2];
    const float* W1w   = (const float*)d_in[3];
    const float* W1b   = (const float*)d_in[4];
    const float* W2w   = (const float*)d_in[5];
    const float* W2b   = (const float*)d_in[6];
    const float* Vw    = (const float*)d_in[7];
    const float* Vb    = (const float*)d_in[8];

    float* out  = (float*)d_out;
    float* ctx  = out;                      // [B, DIM]   = 32768 floats
    float* attn = out + (size_t)BATCH * DIM; // [B, S]    = 65536 floats

    float* qproj;  cudaGetSymbolAddress((void**)&qproj, g_qproj);
    float* score;  cudaGetSymbolAddress((void**)&score, g_score);

    // 1) q_proj: 32768 outputs, one warp each -> 32768 warps -> 4096 blocks
    qproj_kernel<<<4096, 256>>>(query, W1w, W1b, qproj);

    // 2) fused score GEMM: 65536 rows / 128 = 512 CTAs
    score_kernel<<<MROWS / BM, 256>>>(key, W2w, W2b, qproj, Vw, Vb, score);

    // 3) softmax -> attn (written straight into d_out)
    softmax_kernel<<<BATCH, 256>>>(score, attn);

    // 4) context = attn^T @ value
    zero_ctx_kernel<<<BATCH, 1024>>>(ctx);
    context_kernel<<<dim3(BATCH, DIM / 256, 4), 256>>>(attn, value, ctx);
}

// round 4
// speedup vs baseline: 3.2383x; 3.2383x over previous
#include <cuda_runtime.h>
#include <cuda_bf16.h>
#include <math.h>
#include <stdint.h>

#define BATCH 32
#define SEQ   2048
#define DIM   1024
#define MROWS (BATCH * SEQ)   // 65536

// Scratch (no cudaMalloc allowed)
__device__ float g_qproj[BATCH * DIM];
__device__ float g_score[BATCH * SEQ];

// ---------------------------------------------------------------------------
// helpers
// ---------------------------------------------------------------------------
__device__ __forceinline__ uint32_t smem_u32(const void* p) {
    return (uint32_t)__cvta_generic_to_shared(p);
}
__device__ __forceinline__ void ldsm4(uint32_t* r, uint32_t a) {
    asm volatile("ldmatrix.sync.aligned.m8n8.x4.shared.b16 {%0,%1,%2,%3}, [%4];"
                 : "=r"(r[0]), "=r"(r[1]), "=r"(r[2]), "=r"(r[3]) : "r"(a));
}
__device__ __forceinline__ void ldsm2(uint32_t* r, uint32_t a) {
    asm volatile("ldmatrix.sync.aligned.m8n8.x2.shared.b16 {%0,%1}, [%2];"
                 : "=r"(r[0]), "=r"(r[1]) : "r"(a));
}
__device__ __forceinline__ void mma_tf32(float* c, const uint32_t* a, const uint32_t* b) {
    asm volatile(
        "mma.sync.aligned.m16n8k8.row.col.f32.tf32.tf32.f32 "
        "{%0,%1,%2,%3}, {%4,%5,%6,%7}, {%8,%9}, {%0,%1,%2,%3};"
        : "+f"(c[0]), "+f"(c[1]), "+f"(c[2]), "+f"(c[3])
        : "r"(a[0]), "r"(a[1]), "r"(a[2]), "r"(a[3]), "r"(b[0]), "r"(b[1]));
}
__device__ __forceinline__ uint32_t f2tf32(float f) {
    uint32_t o;
    asm("cvt.rna.tf32.f32 %0, %1;" : "=r"(o) : "f"(f));
    return o;
}
__device__ __forceinline__ float tanh_fast(float x) {
    float y;
    asm("tanh.approx.f32 %0, %1;" : "=f"(y) : "f"(x));
    return y;
}
// 16B-chunk swizzled offset within an operand tile: row of 4 chunks (64B),
// chunk index c XORed so both LDSM (8-row phases) and STS (quad c-spread,
// 2-row phases) are bank-conflict-free.
__device__ __forceinline__ int swz(int row, int c) {
    return row * 64 + (((c ^ ((row + (row >> 2)) & 3)) & 3) << 4);
}

// smem layout (dynamic)
#define OFF_A0  0          // 8 KB   (128 rows x 16 k fp32)
#define OFF_B0  8192       // 16 KB  (256 rows x 16 k fp32)
#define OFF_A1  24576
#define OFF_B1  32768
#define OFF_QSM 49152      // 4 KB
#define OFF_VSM 53248      // 4 KB
#define OFF_SC  57344      // 512 B
#define SMEM_TOTAL 57856

// ---------------------------------------------------------------------------
// Kernel 1: q_proj[b,e] = dot(query[b,:], W1[e,:]) + W1_b[e]   (fp32 exact)
// ---------------------------------------------------------------------------
__global__ void qproj_kernel(const float* __restrict__ q,
                             const float* __restrict__ W1,
                             const float* __restrict__ W1b,
                             float* __restrict__ qout) {
    int gw   = (blockIdx.x * blockDim.x + threadIdx.x) >> 5;
    int lane = threadIdx.x & 31;
    if (gw >= BATCH * DIM) return;
    int b = gw >> 10;
    int e = gw & 1023;
    const float4* qr = (const float4*)(q  + (size_t)b * DIM);
    const float4* wr = (const float4*)(W1 + (size_t)e * DIM);
    float acc = 0.f;
#pragma unroll
    for (int i = 0; i < 8; ++i) {
        float4 a = qr[lane + i * 32];
        float4 w = wr[lane + i * 32];
        acc += a.x * w.x + a.y * w.y + a.z * w.z + a.w * w.w;
    }
#pragma unroll
    for (int off = 16; off; off >>= 1)
        acc += __shfl_down_sync(0xffffffffu, acc, off);
    if (lane == 0) qout[gw] = acc + W1b[e];
}

// ---------------------------------------------------------------------------
// Kernel 2 (dominant): tf32 mma.sync fused score GEMM.
//   D[m,n] = key[m,:] . W2[n,:]   (tf32 inputs, fp32 accum)
//   score[m] = Vb + sum_n Vw[n]*tanh(D[m,n] + qproj[b,n] + W2b[n])
// CTA: 128 rows x (4 passes of 256 cols). K-chunk 16, double buffered.
// 8 warps (2m x 4n), warp tile 64x64, per-thread 4x8 m16n8 accum frags.
// ---------------------------------------------------------------------------
__global__ __launch_bounds__(256, 1)
void score_tf32_kernel(const float* __restrict__ key,
                       const float* __restrict__ W2,
                       const float* __restrict__ W2b,
                       const float* __restrict__ qproj,
                       const float* __restrict__ Vw,
                       const float* __restrict__ Vb_p,
                       float* __restrict__ score_g) {
    extern __shared__ char smem[];
    const uint32_t sb = smem_u32(smem);
    float* qsm = (float*)(smem + OFF_QSM);
    float* vsm = (float*)(smem + OFF_VSM);
    float* score_sm = (float*)(smem + OFF_SC);

    const int tid  = threadIdx.x;
    const int lane = tid & 31;
    const int wid  = tid >> 5;
    const int warp_m = wid >> 2;        // 0..1
    const int warp_n = wid & 3;         // 0..3
    const int row0 = blockIdx.x * 128;
    const int b    = row0 >> 11;

    for (int i = tid; i < DIM; i += 256) {
        qsm[i] = qproj[b * DIM + i] + W2b[i];
        vsm[i] = Vw[i];
    }
    if (tid < 128) score_sm[tid] = 0.f;
    __syncthreads();

    // ldmatrix lane constants
    const int r8      = lane & 7;
    const int mlocal  = (((lane >> 3) & 1) << 3) + r8;  // row-in-frag for A x4
    const int a_chalf = lane >> 4;                      // A: col-half select
    const int b_chalf = (lane >> 3) & 1;                // B: col-half select
    const int mrow_t  = warp_m * 64 + mlocal;           // + mf*16
    const int nrow_t  = warp_n * 64 + r8;               // + nf*8

    // global-load lane mapping (quad-coalesced 64B)
    const int gm = tid >> 2;            // 0..63 (+64 per iter)
    const int gc = tid & 3;             // chunk 0..3

    const float* keyA = key + (size_t)row0 * DIM;

    float sp[8];
#pragma unroll
    for (int j = 0; j < 8; ++j) sp[j] = 0.f;

    const uint32_t offA[2] = {OFF_A0, OFF_A1};
    const uint32_t offB[2] = {OFF_B0, OFF_B1};

    for (int nt = 0; nt < 4; ++nt) {
        const float* w2p = W2 + (size_t)(nt * 256) * DIM;

        float acc[4][8][4];
#pragma unroll
        for (int mf = 0; mf < 4; ++mf)
#pragma unroll
            for (int nf = 0; nf < 8; ++nf)
#pragma unroll
                for (int q = 0; q < 4; ++q) acc[mf][nf][q] = 0.f;

        float4 ra[2], rb[4];
        // prologue: chunk 0 -> buf 0
#pragma unroll
        for (int i = 0; i < 2; ++i)
            ra[i] = *(const float4*)(keyA + (size_t)(gm + i * 64) * DIM + gc * 4);
#pragma unroll
        for (int i = 0; i < 4; ++i)
            rb[i] = *(const float4*)(w2p + (size_t)(gm + i * 64) * DIM + gc * 4);
#pragma unroll
        for (int i = 0; i < 2; ++i) {
            uint4 v = { f2tf32(ra[i].x), f2tf32(ra[i].y), f2tf32(ra[i].z), f2tf32(ra[i].w) };
            *(uint4*)(smem + OFF_A0 + swz(gm + i * 64, gc)) = v;
        }
#pragma unroll
        for (int i = 0; i < 4; ++i) {
            uint4 v = { f2tf32(rb[i].x), f2tf32(rb[i].y), f2tf32(rb[i].z), f2tf32(rb[i].w) };
            *(uint4*)(smem + OFF_B0 + swz(gm + i * 64, gc)) = v;
        }
        __syncthreads();

        for (int kc = 0; kc < 64; ++kc) {
            const int buf = kc & 1;
            const bool more = kc < 63;
            if (more) {
                const int k0 = (kc + 1) * 16;
#pragma unroll
                for (int i = 0; i < 2; ++i)
                    ra[i] = *(const float4*)(keyA + (size_t)(gm + i * 64) * DIM + k0 + gc * 4);
#pragma unroll
                for (int i = 0; i < 4; ++i)
                    rb[i] = *(const float4*)(w2p + (size_t)(gm + i * 64) * DIM + k0 + gc * 4);
            }

            const uint32_t ab = sb + offA[buf];
            const uint32_t bb = sb + offB[buf];
#pragma unroll
            for (int s = 0; s < 2; ++s) {
                uint32_t afr[4][4];
                uint32_t bfr[8][2];
#pragma unroll
                for (int mf = 0; mf < 4; ++mf)
                    ldsm4(afr[mf], ab + swz(mrow_t + mf * 16, 2 * s + a_chalf));
#pragma unroll
                for (int nf = 0; nf < 8; ++nf)
                    ldsm2(bfr[nf], bb + swz(nrow_t + nf * 8, 2 * s + b_chalf));
#pragma unroll
                for (int mf = 0; mf < 4; ++mf)
#pragma unroll
                    for (int nf = 0; nf < 8; ++nf)
                        mma_tf32(acc[mf][nf], afr[mf], bfr[nf]);
            }

            if (more) {
                const int nbuf = buf ^ 1;
#pragma unroll
                for (int i = 0; i < 2; ++i) {
                    uint4 v = { f2tf32(ra[i].x), f2tf32(ra[i].y), f2tf32(ra[i].z), f2tf32(ra[i].w) };
                    *(uint4*)(smem + offA[nbuf] + swz(gm + i * 64, gc)) = v;
                }
#pragma unroll
                for (int i = 0; i < 4; ++i) {
                    uint4 v = { f2tf32(rb[i].x), f2tf32(rb[i].y), f2tf32(rb[i].z), f2tf32(rb[i].w) };
                    *(uint4*)(smem + offB[nbuf] + swz(gm + i * 64, gc)) = v;
                }
                __syncthreads();
            }
        }

        // fused epilogue: tanh + V-dot into per-thread row partials
        const int ncol0 = nt * 256 + warp_n * 64 + (lane & 3) * 2;
#pragma unroll
        for (int mf = 0; mf < 4; ++mf) {
#pragma unroll
            for (int nf = 0; nf < 8; ++nf) {
                const int n0 = ncol0 + nf * 8;
                const float q0 = qsm[n0],     v0 = vsm[n0];
                const float q1 = qsm[n0 + 1], v1 = vsm[n0 + 1];
                float* c4 = acc[mf][nf];
                sp[mf * 2 + 0] += tanh_fast(c4[0] + q0) * v0 + tanh_fast(c4[1] + q1) * v1;
                sp[mf * 2 + 1] += tanh_fast(c4[2] + q0) * v0 + tanh_fast(c4[3] + q1) * v1;
            }
        }
        // next nt's prologue STS is gated by its own __syncthreads()
    }

    // reduce quad (lanes sharing the same row) and accumulate to smem
#pragma unroll
    for (int j = 0; j < 8; ++j) {
        float v = sp[j];
        v += __shfl_xor_sync(0xffffffffu, v, 1);
        v += __shfl_xor_sync(0xffffffffu, v, 2);
        if ((lane & 3) == 0) {
            const int row = warp_m * 64 + (j >> 1) * 16 + (j & 1) * 8 + (lane >> 2);
            atomicAdd(&score_sm[row], v);
        }
    }
    __syncthreads();
    if (tid < 128) score_g[row0 + tid] = score_sm[tid] + Vb_p[0];
}

// ---------------------------------------------------------------------------
// Kernel 3: softmax over S per batch row.
// ---------------------------------------------------------------------------
__global__ void softmax_kernel(const float* __restrict__ score,
                               float* __restrict__ attn) {
    const int b   = blockIdx.x;
    const int tid = threadIdx.x;   // 256
    __shared__ float red[256];
    const float* sr = score + (size_t)b * SEQ;

    float v[8];
    float mx = -INFINITY;
#pragma unroll
    for (int i = 0; i < 8; ++i) {
        v[i] = sr[tid + i * 256];
        mx = fmaxf(mx, v[i]);
    }
    red[tid] = mx;
    __syncthreads();
    for (int s = 128; s; s >>= 1) {
        if (tid < s) red[tid] = fmaxf(red[tid], red[tid + s]);
        __syncthreads();
    }
    const float m = red[0];
    __syncthreads();

    float sum = 0.f;
#pragma unroll
    for (int i = 0; i < 8; ++i) {
        v[i] = expf(v[i] - m);
        sum += v[i];
    }
    red[tid] = sum;
    __syncthreads();
    for (int s = 128; s; s >>= 1) {
        if (tid < s) red[tid] += red[tid + s];
        __syncthreads();
    }
    const float inv = 1.f / red[0];
#pragma unroll
    for (int i = 0; i < 8; ++i)
        attn[(size_t)b * SEQ + tid + i * 256] = v[i] * inv;
}

// ---------------------------------------------------------------------------
// Kernel 4a: zero the context region of d_out
// ---------------------------------------------------------------------------
__global__ void zero_ctx_kernel(float* __restrict__ ctx) {
    ctx[(size_t)blockIdx.x * 1024 + threadIdx.x] = 0.f;
}

// ---------------------------------------------------------------------------
// Kernel 4b: context[b,d] += sum_{s chunk} attn[b,s] * value[b,s,d]
// ---------------------------------------------------------------------------
__global__ void context_kernel(const float* __restrict__ attn,
                               const float* __restrict__ value,
                               float* __restrict__ ctx) {
    const int b  = blockIdx.x;
    const int d  = blockIdx.y * 256 + threadIdx.x;
    const int s0 = blockIdx.z * (SEQ / 4);
    const float* vp = value + ((size_t)b * SEQ + s0) * DIM + d;
    const float* ap = attn + (size_t)b * SEQ + s0;
    float acc = 0.f;
#pragma unroll 8
    for (int s = 0; s < SEQ / 4; ++s)
        acc = fmaf(__ldg(ap + s), vp[(size_t)s * DIM], acc);
    atomicAdd(&ctx[(size_t)b * DIM + d], acc);
}

// ---------------------------------------------------------------------------
extern "C" void kernel_launch(void* const* d_in, const int* in_sizes, int n_in,
                              void* d_out, int out_size) {
    const float* query = (const float*)d_in[0];
    const float* key   = (const float*)d_in[1];
    const float* value = (const float*)d_in[2];
    const float* W1w   = (const float*)d_in[3];
    const float* W1b   = (const float*)d_in[4];
    const float* W2w   = (const float*)d_in[5];
    const float* W2b   = (const float*)d_in[6];
    const float* Vw    = (const float*)d_in[7];
    const float* Vb    = (const float*)d_in[8];

    float* out  = (float*)d_out;
    float* ctx  = out;                        // [B, DIM]
    float* attn = out + (size_t)BATCH * DIM;  // [B, S]

    float* qproj;  cudaGetSymbolAddress((void**)&qproj, g_qproj);
    float* score;  cudaGetSymbolAddress((void**)&score, g_score);

    // 1) q_proj (fp32 exact)
    qproj_kernel<<<4096, 256>>>(query, W1w, W1b, qproj);

    // 2) tf32 mma.sync fused score GEMM
    cudaFuncSetAttribute(score_tf32_kernel,
                         cudaFuncAttributeMaxDynamicSharedMemorySize, SMEM_TOTAL);
    score_tf32_kernel<<<MROWS / 128, 256, SMEM_TOTAL>>>(key, W2w, W2b, qproj,
                                                        Vw, Vb, score);

    // 3) softmax -> attn
    softmax_kernel<<<BATCH, 256>>>(score, attn);

    // 4) context = attn^T @ value
    zero_ctx_kernel<<<BATCH, 1024>>>(ctx);
    context_kernel<<<dim3(BATCH, DIM / 256, 4), 256>>>(attn, value, ctx);
}

// round 5
// speedup vs baseline: 5.6556x; 1.7465x over previous
#include <cuda_runtime.h>
#include <cuda_bf16.h>
#include <cuda_fp16.h>
#include <math.h>
#include <stdint.h>

#define BATCH 32
#define SEQ   2048
#define DIM   1024
#define MROWS (BATCH * SEQ)   // 65536

// Scratch (no cudaMalloc allowed)
__device__ float g_qproj[BATCH * DIM];
__device__ float g_score[BATCH * SEQ];

// ---------------------------------------------------------------------------
// helpers
// ---------------------------------------------------------------------------
__device__ __forceinline__ uint32_t smem_u32(const void* p) {
    return (uint32_t)__cvta_generic_to_shared(p);
}
__device__ __forceinline__ void ldsm4(uint32_t* r, uint32_t a) {
    asm volatile("ldmatrix.sync.aligned.m8n8.x4.shared.b16 {%0,%1,%2,%3}, [%4];"
                 : "=r"(r[0]), "=r"(r[1]), "=r"(r[2]), "=r"(r[3]) : "r"(a));
}
__device__ __forceinline__ void ldsm2(uint32_t* r, uint32_t a) {
    asm volatile("ldmatrix.sync.aligned.m8n8.x2.shared.b16 {%0,%1}, [%2];"
                 : "=r"(r[0]), "=r"(r[1]) : "r"(a));
}
// fp16 m16n8k16, fp32 accumulate
__device__ __forceinline__ void mma_f16(float* c, const uint32_t* a, const uint32_t* b) {
    asm volatile(
        "mma.sync.aligned.m16n8k16.row.col.f32.f16.f16.f32 "
        "{%0,%1,%2,%3}, {%4,%5,%6,%7}, {%8,%9}, {%0,%1,%2,%3};"
        : "+f"(c[0]), "+f"(c[1]), "+f"(c[2]), "+f"(c[3])
        : "r"(a[0]), "r"(a[1]), "r"(a[2]), "r"(a[3]), "r"(b[0]), "r"(b[1]));
}
__device__ __forceinline__ uint32_t packh2(float lo, float hi) {
    __half2 h = __floats2half2_rn(lo, hi);
    return *(uint32_t*)&h;
}
__device__ __forceinline__ float tanh_fast(float x) {
    float y;
    asm("tanh.approx.f32 %0, %1;" : "=f"(y) : "f"(x));
    return y;
}
// 16B-chunk swizzled offset within an operand tile: row of 4 chunks (64B),
// chunk index c XORed so both LDSM (8-row phases) and STS (quad c-spread)
// are bank-conflict-free. (Identical geometry to the verified tf32 kernel.)
__device__ __forceinline__ int swz(int row, int c) {
    return row * 64 + (((c ^ ((row + (row >> 2)) & 3)) & 3) << 4);
}

// smem layout (dynamic). fp16 with K-chunk 32 keeps the exact tf32 sizes:
// A tile 128 rows x 64B, B tile 256 rows x 64B.
#define OFF_A0  0          // 8 KB
#define OFF_B0  8192       // 16 KB
#define OFF_A1  24576
#define OFF_B1  32768
#define OFF_QSM 49152      // 4 KB
#define OFF_VSM 53248      // 4 KB
#define OFF_SC  57344      // 512 B
#define SMEM_TOTAL 57856

// ---------------------------------------------------------------------------
// Kernel 1: q_proj[b,e] = dot(query[b,:], W1[e,:]) + W1_b[e]   (fp32 exact)
// ---------------------------------------------------------------------------
__global__ void qproj_kernel(const float* __restrict__ q,
                             const float* __restrict__ W1,
                             const float* __restrict__ W1b,
                             float* __restrict__ qout) {
    int gw   = (blockIdx.x * blockDim.x + threadIdx.x) >> 5;
    int lane = threadIdx.x & 31;
    if (gw >= BATCH * DIM) return;
    int b = gw >> 10;
    int e = gw & 1023;
    const float4* qr = (const float4*)(q  + (size_t)b * DIM);
    const float4* wr = (const float4*)(W1 + (size_t)e * DIM);
    float acc = 0.f;
#pragma unroll
    for (int i = 0; i < 8; ++i) {
        float4 a = qr[lane + i * 32];
        float4 w = wr[lane + i * 32];
        acc += a.x * w.x + a.y * w.y + a.z * w.z + a.w * w.w;
    }
#pragma unroll
    for (int off = 16; off; off >>= 1)
        acc += __shfl_down_sync(0xffffffffu, acc, off);
    if (lane == 0) qout[gw] = acc + W1b[e];
}

// ---------------------------------------------------------------------------
// Kernel 2 (dominant): fp16 mma.sync fused score GEMM.
//   D[m,n] = key[m,:] . W2[n,:]   (fp16 inputs, fp32 accum)
//   score[m] = Vb + sum_n Vw[n]*tanh(D[m,n] + qproj[b,n] + W2b[n])
// CTA: 128 rows x (4 passes of 256 cols). K-chunk 32 fp16, double buffered.
// 8 warps (2m x 4n), warp tile 64x64, per-thread 4x8 m16n8 accum frags.
// ---------------------------------------------------------------------------
__global__ __launch_bounds__(256, 1)
void score_f16_kernel(const float* __restrict__ key,
                      const float* __restrict__ W2,
                      const float* __restrict__ W2b,
                      const float* __restrict__ qproj,
                      const float* __restrict__ Vw,
                      const float* __restrict__ Vb_p,
                      float* __restrict__ score_g) {
    extern __shared__ char smem[];
    const uint32_t sb = smem_u32(smem);
    float* qsm = (float*)(smem + OFF_QSM);
    float* vsm = (float*)(smem + OFF_VSM);
    float* score_sm = (float*)(smem + OFF_SC);

    const int tid  = threadIdx.x;
    const int lane = tid & 31;
    const int wid  = tid >> 5;
    const int warp_m = wid >> 2;        // 0..1
    const int warp_n = wid & 3;         // 0..3
    const int row0 = blockIdx.x * 128;
    const int b    = row0 >> 11;

    for (int i = tid; i < DIM; i += 256) {
        qsm[i] = qproj[b * DIM + i] + W2b[i];
        vsm[i] = Vw[i];
    }
    if (tid < 128) score_sm[tid] = 0.f;
    __syncthreads();

    // ldmatrix lane constants (chunk = 8 fp16 = one k8 half of a k16 step)
    const int r8      = lane & 7;
    const int mlocal  = (((lane >> 3) & 1) << 3) + r8;  // A x4 row-in-frag
    const int a_chalf = lane >> 4;                      // A: k8-half select
    const int b_chalf = (lane >> 3) & 1;                // B: k8-half select
    const int mrow_t  = warp_m * 64 + mlocal;           // + mf*16
    const int nrow_t  = warp_n * 64 + r8;               // + nf*8

    // global-load lane mapping: thread -> (row, 16B-fp16 chunk) = 8 fp32
    const int gm = tid >> 2;            // 0..63 (+64 per iter)
    const int gc = tid & 3;             // chunk 0..3

    const float* keyA = key + (size_t)row0 * DIM;

    float sp[8];
#pragma unroll
    for (int j = 0; j < 8; ++j) sp[j] = 0.f;

    const uint32_t offA[2] = {OFF_A0, OFF_A1};
    const uint32_t offB[2] = {OFF_B0, OFF_B1};

    for (int nt = 0; nt < 4; ++nt) {
        const float* w2p = W2 + (size_t)(nt * 256) * DIM;

        float acc[4][8][4];
#pragma unroll
        for (int mf = 0; mf < 4; ++mf)
#pragma unroll
            for (int nf = 0; nf < 8; ++nf)
#pragma unroll
                for (int q = 0; q < 4; ++q) acc[mf][nf][q] = 0.f;

        float4 ra[2][2], rb[4][2];
        // prologue: k-chunk 0 -> buf 0
#pragma unroll
        for (int i = 0; i < 2; ++i) {
            const float* p = keyA + (size_t)(gm + i * 64) * DIM + gc * 8;
            ra[i][0] = *(const float4*)p;
            ra[i][1] = *(const float4*)(p + 4);
        }
#pragma unroll
        for (int i = 0; i < 4; ++i) {
            const float* p = w2p + (size_t)(gm + i * 64) * DIM + gc * 8;
            rb[i][0] = *(const float4*)p;
            rb[i][1] = *(const float4*)(p + 4);
        }
#pragma unroll
        for (int i = 0; i < 2; ++i) {
            uint4 v = { packh2(ra[i][0].x, ra[i][0].y), packh2(ra[i][0].z, ra[i][0].w),
                        packh2(ra[i][1].x, ra[i][1].y), packh2(ra[i][1].z, ra[i][1].w) };
            *(uint4*)(smem + OFF_A0 + swz(gm + i * 64, gc)) = v;
        }
#pragma unroll
        for (int i = 0; i < 4; ++i) {
            uint4 v = { packh2(rb[i][0].x, rb[i][0].y), packh2(rb[i][0].z, rb[i][0].w),
                        packh2(rb[i][1].x, rb[i][1].y), packh2(rb[i][1].z, rb[i][1].w) };
            *(uint4*)(smem + OFF_B0 + swz(gm + i * 64, gc)) = v;
        }
        __syncthreads();

        for (int kc = 0; kc < 32; ++kc) {          // 32 chunks of K=32 fp16
            const int buf = kc & 1;
            const bool more = kc < 31;
            if (more) {
                const int k0 = (kc + 1) * 32;
#pragma unroll
                for (int i = 0; i < 2; ++i) {
                    const float* p = keyA + (size_t)(gm + i * 64) * DIM + k0 + gc * 8;
                    ra[i][0] = *(const float4*)p;
                    ra[i][1] = *(const float4*)(p + 4);
                }
#pragma unroll
                for (int i = 0; i < 4; ++i) {
                    const float* p = w2p + (size_t)(gm + i * 64) * DIM + k0 + gc * 8;
                    rb[i][0] = *(const float4*)p;
                    rb[i][1] = *(const float4*)(p + 4);
                }
            }

            const uint32_t ab = sb + offA[buf];
            const uint32_t bb = sb + offB[buf];
#pragma unroll
            for (int s = 0; s < 2; ++s) {          // two k16 MMA steps
                uint32_t afr[4][4];
                uint32_t bfr[8][2];
#pragma unroll
                for (int mf = 0; mf < 4; ++mf)
                    ldsm4(afr[mf], ab + swz(mrow_t + mf * 16, 2 * s + a_chalf));
#pragma unroll
                for (int nf = 0; nf < 8; ++nf)
                    ldsm2(bfr[nf], bb + swz(nrow_t + nf * 8, 2 * s + b_chalf));
#pragma unroll
                for (int mf = 0; mf < 4; ++mf)
#pragma unroll
                    for (int nf = 0; nf < 8; ++nf)
                        mma_f16(acc[mf][nf], afr[mf], bfr[nf]);
            }

            if (more) {
                const int nbuf = buf ^ 1;
#pragma unroll
                for (int i = 0; i < 2; ++i) {
                    uint4 v = { packh2(ra[i][0].x, ra[i][0].y), packh2(ra[i][0].z, ra[i][0].w),
                                packh2(ra[i][1].x, ra[i][1].y), packh2(ra[i][1].z, ra[i][1].w) };
                    *(uint4*)(smem + offA[nbuf] + swz(gm + i * 64, gc)) = v;
                }
#pragma unroll
                for (int i = 0; i < 4; ++i) {
                    uint4 v = { packh2(rb[i][0].x, rb[i][0].y), packh2(rb[i][0].z, rb[i][0].w),
                                packh2(rb[i][1].x, rb[i][1].y), packh2(rb[i][1].z, rb[i][1].w) };
                    *(uint4*)(smem + offB[nbuf] + swz(gm + i * 64, gc)) = v;
                }
                __syncthreads();
            }
        }

        // fused epilogue: tanh + V-dot into per-thread row partials
        const int ncol0 = nt * 256 + warp_n * 64 + (lane & 3) * 2;
#pragma unroll
        for (int mf = 0; mf < 4; ++mf) {
#pragma unroll
            for (int nf = 0; nf < 8; ++nf) {
                const int n0 = ncol0 + nf * 8;
                const float q0 = qsm[n0],     v0 = vsm[n0];
                const float q1 = qsm[n0 + 1], v1 = vsm[n0 + 1];
                float* c4 = acc[mf][nf];
                sp[mf * 2 + 0] += tanh_fast(c4[0] + q0) * v0 + tanh_fast(c4[1] + q1) * v1;
                sp[mf * 2 + 1] += tanh_fast(c4[2] + q0) * v0 + tanh_fast(c4[3] + q1) * v1;
            }
        }
        // next nt's prologue STS targets buf0; gated by its own __syncthreads()
    }

    // reduce quad (lanes sharing the same row) and accumulate to smem
#pragma unroll
    for (int j = 0; j < 8; ++j) {
        float v = sp[j];
        v += __shfl_xor_sync(0xffffffffu, v, 1);
        v += __shfl_xor_sync(0xffffffffu, v, 2);
        if ((lane & 3) == 0) {
            const int row = warp_m * 64 + (j >> 1) * 16 + (j & 1) * 8 + (lane >> 2);
            atomicAdd(&score_sm[row], v);
        }
    }
    __syncthreads();
    if (tid < 128) score_g[row0 + tid] = score_sm[tid] + Vb_p[0];
}

// ---------------------------------------------------------------------------
// Kernel 3: softmax over S per batch row.
// ---------------------------------------------------------------------------
__global__ void softmax_kernel(const float* __restrict__ score,
                               float* __restrict__ attn) {
    const int b   = blockIdx.x;
    const int tid = threadIdx.x;   // 256
    __shared__ float red[256];
    const float* sr = score + (size_t)b * SEQ;

    float v[8];
    float mx = -INFINITY;
#pragma unroll
    for (int i = 0; i < 8; ++i) {
        v[i] = sr[tid + i * 256];
        mx = fmaxf(mx, v[i]);
    }
    red[tid] = mx;
    __syncthreads();
    for (int s = 128; s; s >>= 1) {
        if (tid < s) red[tid] = fmaxf(red[tid], red[tid + s]);
        __syncthreads();
    }
    const float m = red[0];
    __syncthreads();

    float sum = 0.f;
#pragma unroll
    for (int i = 0; i < 8; ++i) {
        v[i] = expf(v[i] - m);
        sum += v[i];
    }
    red[tid] = sum;
    __syncthreads();
    for (int s = 128; s; s >>= 1) {
        if (tid < s) red[tid] += red[tid + s];
        __syncthreads();
    }
    const float inv = 1.f / red[0];
#pragma unroll
    for (int i = 0; i < 8; ++i)
        attn[(size_t)b * SEQ + tid + i * 256] = v[i] * inv;
}

// ---------------------------------------------------------------------------
// Kernel 4a: zero the context region of d_out
// ---------------------------------------------------------------------------
__global__ void zero_ctx_kernel(float* __restrict__ ctx) {
    ctx[(size_t)blockIdx.x * 1024 + threadIdx.x] = 0.f;
}

// ---------------------------------------------------------------------------
// Kernel 4b: context[b,d] += sum_{s chunk} attn[b,s] * value[b,s,d]
// ---------------------------------------------------------------------------
__global__ void context_kernel(const float* __restrict__ attn,
                               const float* __restrict__ value,
                               float* __restrict__ ctx) {
    const int b  = blockIdx.x;
    const int d  = blockIdx.y * 256 + threadIdx.x;
    const int s0 = blockIdx.z * (SEQ / 4);
    const float* vp = value + ((size_t)b * SEQ + s0) * DIM + d;
    const float* ap = attn + (size_t)b * SEQ + s0;
    float acc = 0.f;
#pragma unroll 8
    for (int s = 0; s < SEQ / 4; ++s)
        acc = fmaf(__ldg(ap + s), vp[(size_t)s * DIM], acc);
    atomicAdd(&ctx[(size_t)b * DIM + d], acc);
}

// ---------------------------------------------------------------------------
extern "C" void kernel_launch(void* const* d_in, const int* in_sizes, int n_in,
                              void* d_out, int out_size) {
    const float* query = (const float*)d_in[0];
    const float* key   = (const float*)d_in[1];
    const float* value = (const float*)d_in[2];
    const float* W1w   = (const float*)d_in[3];
    const float* W1b   = (const float*)d_in[4];
    const float* W2w   = (const float*)d_in[5];
    const float* W2b   = (const float*)d_in[6];
    const float* Vw    = (const float*)d_in[7];
    const float* Vb    = (const float*)d_in[8];

    float* out  = (float*)d_out;
    float* ctx  = out;                        // [B, DIM]
    float* attn = out + (size_t)BATCH * DIM;  // [B, S]

    float* qproj;  cudaGetSymbolAddress((void**)&qproj, g_qproj);
    float* score;  cudaGetSymbolAddress((void**)&score, g_score);

    // 1) q_proj (fp32 exact)
    qproj_kernel<<<4096, 256>>>(query, W1w, W1b, qproj);

    // 2) fp16 mma.sync fused score GEMM
    cudaFuncSetAttribute(score_f16_kernel,
                         cudaFuncAttributeMaxDynamicSharedMemorySize, SMEM_TOTAL);
    score_f16_kernel<<<MROWS / 128, 256, SMEM_TOTAL>>>(key, W2w, W2b, qproj,
                                                       Vw, Vb, score);

    // 3) softmax -> attn
    softmax_kernel<<<BATCH, 256>>>(score, attn);

    // 4) context = attn^T @ value
    zero_ctx_kernel<<<BATCH, 1024>>>(ctx);
    context_kernel<<<dim3(BATCH, DIM / 256, 4), 256>>>(attn, value, ctx);
}

// round 6
// speedup vs baseline: 6.0935x; 1.0774x over previous
#include <cuda_runtime.h>
#include <cuda_bf16.h>
#include <cuda_fp16.h>
#include <math.h>
#include <stdint.h>

#define BATCH 32
#define SEQ   2048
#define DIM   1024
#define MROWS (BATCH * SEQ)   // 65536

// Scratch (no cudaMalloc allowed)
__device__ float g_qproj[BATCH * DIM];
__device__ float g_score[BATCH * SEQ];

// ---------------------------------------------------------------------------
// helpers
// ---------------------------------------------------------------------------
__device__ __forceinline__ uint32_t smem_u32(const void* p) {
    return (uint32_t)__cvta_generic_to_shared(p);
}
__device__ __forceinline__ void ldsm4(uint32_t* r, uint32_t a) {
    asm volatile("ldmatrix.sync.aligned.m8n8.x4.shared.b16 {%0,%1,%2,%3}, [%4];"
                 : "=r"(r[0]), "=r"(r[1]), "=r"(r[2]), "=r"(r[3]) : "r"(a));
}
__device__ __forceinline__ void ldsm2(uint32_t* r, uint32_t a) {
    asm volatile("ldmatrix.sync.aligned.m8n8.x2.shared.b16 {%0,%1}, [%2];"
                 : "=r"(r[0]), "=r"(r[1]) : "r"(a));
}
// fp16 m16n8k16, fp32 accumulate
__device__ __forceinline__ void mma_f16(float* c, const uint32_t* a, const uint32_t* b) {
    asm volatile(
        "mma.sync.aligned.m16n8k16.row.col.f32.f16.f16.f32 "
        "{%0,%1,%2,%3}, {%4,%5,%6,%7}, {%8,%9}, {%0,%1,%2,%3};"
        : "+f"(c[0]), "+f"(c[1]), "+f"(c[2]), "+f"(c[3])
        : "r"(a[0]), "r"(a[1]), "r"(a[2]), "r"(a[3]), "r"(b[0]), "r"(b[1]));
}
__device__ __forceinline__ uint32_t packh2(float lo, float hi) {
    __half2 h = __floats2half2_rn(lo, hi);
    return *(uint32_t*)&h;
}
__device__ __forceinline__ float tanh_fast(float x) {
    float y;
    asm("tanh.approx.f32 %0, %1;" : "=f"(y) : "f"(x));
    return y;
}
// 16B-chunk swizzled offset within an operand tile: row of 4 chunks (64B),
// chunk index c XORed so both LDSM (8-row phases) and STS (quad c-spread)
// are bank-conflict-free.
__device__ __forceinline__ int swz(int row, int c) {
    return row * 64 + (((c ^ ((row + (row >> 2)) & 3)) & 3) << 4);
}

// smem layout (dynamic). fp16 with K-chunk 32:
// A tile 128 rows x 64B, B tile 256 rows x 64B.
#define OFF_A0  0          // 8 KB
#define OFF_B0  8192       // 16 KB
#define OFF_A1  24576
#define OFF_B1  32768
#define OFF_QSM 49152      // 4 KB
#define OFF_VSM 53248      // 4 KB
#define OFF_SC  57344      // 512 B
#define SMEM_TOTAL 57856

// ---------------------------------------------------------------------------
// Kernel 0: zero ctx region of d_out and g_score (poisoned / accumulated into)
// grid 96 x 1024 covers 98304 floats: first 32768 -> ctx, rest -> score
// ---------------------------------------------------------------------------
__global__ void zero_kernel(float* __restrict__ ctx, float* __restrict__ score) {
    int i = blockIdx.x * 1024 + threadIdx.x;
    if (i < BATCH * DIM) ctx[i] = 0.f;
    else                 score[i - BATCH * DIM] = 0.f;
}

// ---------------------------------------------------------------------------
// Kernel 1: q_proj[b,e] = dot(query[b,:], W1[e,:]) + W1_b[e]   (fp32 exact)
// ---------------------------------------------------------------------------
__global__ void qproj_kernel(const float* __restrict__ q,
                             const float* __restrict__ W1,
                             const float* __restrict__ W1b,
                             float* __restrict__ qout) {
    int gw   = (blockIdx.x * blockDim.x + threadIdx.x) >> 5;
    int lane = threadIdx.x & 31;
    if (gw >= BATCH * DIM) return;
    int b = gw >> 10;
    int e = gw & 1023;
    const float4* qr = (const float4*)(q  + (size_t)b * DIM);
    const float4* wr = (const float4*)(W1 + (size_t)e * DIM);
    float acc = 0.f;
#pragma unroll
    for (int i = 0; i < 8; ++i) {
        float4 a = qr[lane + i * 32];
        float4 w = wr[lane + i * 32];
        acc += a.x * w.x + a.y * w.y + a.z * w.z + a.w * w.w;
    }
#pragma unroll
    for (int off = 16; off; off >>= 1)
        acc += __shfl_down_sync(0xffffffffu, acc, off);
    if (lane == 0) qout[gw] = acc + W1b[e];
}

// ---------------------------------------------------------------------------
// Kernel 2 (dominant): fp16 mma.sync fused score GEMM, nt-split over
// blockIdx.y to shrink wave-tail quantization.
//   D[m,n] = key[m,:] . W2[n,:]   (fp16 inputs, fp32 accum)
//   score[m] += sum_{n in half} Vw[n]*tanh(D[m,n] + qproj[b,n] + W2b[n])
// (V_b dropped: softmax is shift-invariant and score is not an output.)
// CTA: 128 rows x (2 passes of 256 cols). K-chunk 32 fp16, double buffered.
// 8 warps (2m x 4n), warp tile 64x64, per-thread 4x8 m16n8 accum frags.
// ---------------------------------------------------------------------------
__global__ __launch_bounds__(256, 1)
void score_f16_kernel(const float* __restrict__ key,
                      const float* __restrict__ W2,
                      const float* __restrict__ W2b,
                      const float* __restrict__ qproj,
                      const float* __restrict__ Vw,
                      float* __restrict__ score_g) {
    extern __shared__ char smem[];
    const uint32_t sb = smem_u32(smem);
    float* qsm = (float*)(smem + OFF_QSM);
    float* vsm = (float*)(smem + OFF_VSM);
    float* score_sm = (float*)(smem + OFF_SC);

    const int tid  = threadIdx.x;
    const int lane = tid & 31;
    const int wid  = tid >> 5;
    const int warp_m = wid >> 2;        // 0..1
    const int warp_n = wid & 3;         // 0..3
    const int row0 = blockIdx.x * 128;
    const int b    = row0 >> 11;
    const int nt0  = blockIdx.y * 2;    // this CTA's nt range: nt0, nt0+1

    for (int i = tid; i < DIM; i += 256) {
        qsm[i] = qproj[b * DIM + i] + W2b[i];
        vsm[i] = Vw[i];
    }
    if (tid < 128) score_sm[tid] = 0.f;
    __syncthreads();

    // ldmatrix lane constants (chunk = 8 fp16 = one k8 half of a k16 step)
    const int r8      = lane & 7;
    const int mlocal  = (((lane >> 3) & 1) << 3) + r8;  // A x4 row-in-frag
    const int a_chalf = lane >> 4;                      // A: k8-half select
    const int b_chalf = (lane >> 3) & 1;                // B: k8-half select
    const int mrow_t  = warp_m * 64 + mlocal;           // + mf*16
    const int nrow_t  = warp_n * 64 + r8;               // + nf*8

    // global-load lane mapping: thread -> (row, 16B-fp16 chunk) = 8 fp32
    const int gm = tid >> 2;            // 0..63 (+64 per iter)
    const int gc = tid & 3;             // chunk 0..3

    const float* keyA = key + (size_t)row0 * DIM;

    float sp[8];
#pragma unroll
    for (int j = 0; j < 8; ++j) sp[j] = 0.f;

    const uint32_t offA[2] = {OFF_A0, OFF_A1};
    const uint32_t offB[2] = {OFF_B0, OFF_B1};

    for (int p = 0; p < 2; ++p) {
        const int nt = nt0 + p;
        const float* w2p = W2 + (size_t)(nt * 256) * DIM;

        float acc[4][8][4];
#pragma unroll
        for (int mf = 0; mf < 4; ++mf)
#pragma unroll
            for (int nf = 0; nf < 8; ++nf)
#pragma unroll
                for (int q = 0; q < 4; ++q) acc[mf][nf][q] = 0.f;

        float4 ra[2][2], rb[4][2];
        // prologue: k-chunk 0 -> buf 0
#pragma unroll
        for (int i = 0; i < 2; ++i) {
            const float* pp = keyA + (size_t)(gm + i * 64) * DIM + gc * 8;
            ra[i][0] = *(const float4*)pp;
            ra[i][1] = *(const float4*)(pp + 4);
        }
#pragma unroll
        for (int i = 0; i < 4; ++i) {
            const float* pp = w2p + (size_t)(gm + i * 64) * DIM + gc * 8;
            rb[i][0] = *(const float4*)pp;
            rb[i][1] = *(const float4*)(pp + 4);
        }
#pragma unroll
        for (int i = 0; i < 2; ++i) {
            uint4 v = { packh2(ra[i][0].x, ra[i][0].y), packh2(ra[i][0].z, ra[i][0].w),
                        packh2(ra[i][1].x, ra[i][1].y), packh2(ra[i][1].z, ra[i][1].w) };
            *(uint4*)(smem + OFF_A0 + swz(gm + i * 64, gc)) = v;
        }
#pragma unroll
        for (int i = 0; i < 4; ++i) {
            uint4 v = { packh2(rb[i][0].x, rb[i][0].y), packh2(rb[i][0].z, rb[i][0].w),
                        packh2(rb[i][1].x, rb[i][1].y), packh2(rb[i][1].z, rb[i][1].w) };
            *(uint4*)(smem + OFF_B0 + swz(gm + i * 64, gc)) = v;
        }
        __syncthreads();

        for (int kc = 0; kc < 32; ++kc) {          // 32 chunks of K=32 fp16
            const int buf = kc & 1;
            const bool more = kc < 31;
            if (more) {
                const int k0 = (kc + 1) * 32;
#pragma unroll
                for (int i = 0; i < 2; ++i) {
                    const float* pp = keyA + (size_t)(gm + i * 64) * DIM + k0 + gc * 8;
                    ra[i][0] = *(const float4*)pp;
                    ra[i][1] = *(const float4*)(pp + 4);
                }
#pragma unroll
                for (int i = 0; i < 4; ++i) {
                    const float* pp = w2p + (size_t)(gm + i * 64) * DIM + k0 + gc * 8;
                    rb[i][0] = *(const float4*)pp;
                    rb[i][1] = *(const float4*)(pp + 4);
                }
            }

            const uint32_t ab = sb + offA[buf];
            const uint32_t bb = sb + offB[buf];
#pragma unroll
            for (int s = 0; s < 2; ++s) {          // two k16 MMA steps
                uint32_t afr[4][4];
                uint32_t bfr[8][2];
#pragma unroll
                for (int mf = 0; mf < 4; ++mf)
                    ldsm4(afr[mf], ab + swz(mrow_t + mf * 16, 2 * s + a_chalf));
#pragma unroll
                for (int nf = 0; nf < 8; ++nf)
                    ldsm2(bfr[nf], bb + swz(nrow_t + nf * 8, 2 * s + b_chalf));
#pragma unroll
                for (int mf = 0; mf < 4; ++mf)
#pragma unroll
                    for (int nf = 0; nf < 8; ++nf)
                        mma_f16(acc[mf][nf], afr[mf], bfr[nf]);
            }

            if (more) {
                const int nbuf = buf ^ 1;
#pragma unroll
                for (int i = 0; i < 2; ++i) {
                    uint4 v = { packh2(ra[i][0].x, ra[i][0].y), packh2(ra[i][0].z, ra[i][0].w),
                                packh2(ra[i][1].x, ra[i][1].y), packh2(ra[i][1].z, ra[i][1].w) };
                    *(uint4*)(smem + offA[nbuf] + swz(gm + i * 64, gc)) = v;
                }
#pragma unroll
                for (int i = 0; i < 4; ++i) {
                    uint4 v = { packh2(rb[i][0].x, rb[i][0].y), packh2(rb[i][0].z, rb[i][0].w),
                                packh2(rb[i][1].x, rb[i][1].y), packh2(rb[i][1].z, rb[i][1].w) };
                    *(uint4*)(smem + offB[nbuf] + swz(gm + i * 64, gc)) = v;
                }
                __syncthreads();
            }
        }

        // fused epilogue: tanh + V-dot into per-thread row partials
        const int ncol0 = nt * 256 + warp_n * 64 + (lane & 3) * 2;
#pragma unroll
        for (int mf = 0; mf < 4; ++mf) {
#pragma unroll
            for (int nf = 0; nf < 8; ++nf) {
                const int n0 = ncol0 + nf * 8;
                const float q0 = qsm[n0],     v0 = vsm[n0];
                const float q1 = qsm[n0 + 1], v1 = vsm[n0 + 1];
                float* c4 = acc[mf][nf];
                sp[mf * 2 + 0] += tanh_fast(c4[0] + q0) * v0 + tanh_fast(c4[1] + q1) * v1;
                sp[mf * 2 + 1] += tanh_fast(c4[2] + q0) * v0 + tanh_fast(c4[3] + q1) * v1;
            }
        }
        // next pass's prologue STS targets buf0; gated by its own __syncthreads()
    }

    // reduce quad (lanes sharing the same row) and accumulate to smem
#pragma unroll
    for (int j = 0; j < 8; ++j) {
        float v = sp[j];
        v += __shfl_xor_sync(0xffffffffu, v, 1);
        v += __shfl_xor_sync(0xffffffffu, v, 2);
        if ((lane & 3) == 0) {
            const int row = warp_m * 64 + (j >> 1) * 16 + (j & 1) * 8 + (lane >> 2);
            atomicAdd(&score_sm[row], v);
        }
    }
    __syncthreads();
    if (tid < 128) atomicAdd(&score_g[row0 + tid], score_sm[tid]);
}

// ---------------------------------------------------------------------------
// Kernel 3: softmax over S per batch row.
// ---------------------------------------------------------------------------
__global__ void softmax_kernel(const float* __restrict__ score,
                               float* __restrict__ attn) {
    const int b   = blockIdx.x;
    const int tid = threadIdx.x;   // 256
    __shared__ float red[256];
    const float* sr = score + (size_t)b * SEQ;

    float v[8];
    float mx = -INFINITY;
#pragma unroll
    for (int i = 0; i < 8; ++i) {
        v[i] = sr[tid + i * 256];
        mx = fmaxf(mx, v[i]);
    }
    red[tid] = mx;
    __syncthreads();
    for (int s = 128; s; s >>= 1) {
        if (tid < s) red[tid] = fmaxf(red[tid], red[tid + s]);
        __syncthreads();
    }
    const float m = red[0];
    __syncthreads();

    float sum = 0.f;
#pragma unroll
    for (int i = 0; i < 8; ++i) {
        v[i] = expf(v[i] - m);
        sum += v[i];
    }
    red[tid] = sum;
    __syncthreads();
    for (int s = 128; s; s >>= 1) {
        if (tid < s) red[tid] += red[tid + s];
        __syncthreads();
    }
    const float inv = 1.f / red[0];
#pragma unroll
    for (int i = 0; i < 8; ++i)
        attn[(size_t)b * SEQ + tid + i * 256] = v[i] * inv;
}

// ---------------------------------------------------------------------------
// Kernel 4: context[b,d] += sum_{s chunk} attn[b,s] * value[b,s,d]
// ---------------------------------------------------------------------------
__global__ void context_kernel(const float* __restrict__ attn,
                               const float* __restrict__ value,
                               float* __restrict__ ctx) {
    const int b  = blockIdx.x;
    const int d  = blockIdx.y * 256 + threadIdx.x;
    const int s0 = blockIdx.z * (SEQ / 4);
    const float* vp = value + ((size_t)b * SEQ + s0) * DIM + d;
    const float* ap = attn + (size_t)b * SEQ + s0;
    float acc = 0.f;
#pragma unroll 8
    for (int s = 0; s < SEQ / 4; ++s)
        acc = fmaf(__ldg(ap + s), vp[(size_t)s * DIM], acc);
    atomicAdd(&ctx[(size_t)b * DIM + d], acc);
}

// ---------------------------------------------------------------------------
extern "C" void kernel_launch(void* const* d_in, const int* in_sizes, int n_in,
                              void* d_out, int out_size) {
    const float* query = (const float*)d_in[0];
    const float* key   = (const float*)d_in[1];
    const float* value = (const float*)d_in[2];
    const float* W1w   = (const float*)d_in[3];
    const float* W1b   = (const float*)d_in[4];
    const float* W2w   = (const float*)d_in[5];
    const float* W2b   = (const float*)d_in[6];
    const float* Vw    = (const float*)d_in[7];
    // d_in[8] = V_b: dropped — softmax is shift-invariant, score not an output

    float* out  = (float*)d_out;
    float* ctx  = out;                        // [B, DIM]
    float* attn = out + (size_t)BATCH * DIM;  // [B, S]

    float* qproj;  cudaGetSymbolAddress((void**)&qproj, g_qproj);
    float* score;  cudaGetSymbolAddress((void**)&score, g_score);

    // 0) zero ctx + score accumulators
    zero_kernel<<<96, 1024>>>(ctx, score);

    // 1) q_proj (fp32 exact)
    qproj_kernel<<<4096, 256>>>(query, W1w, W1b, qproj);

    // 2) fp16 mma.sync fused score GEMM, nt-split x2 for tail reduction
    cudaFuncSetAttribute(score_f16_kernel,
                         cudaFuncAttributeMaxDynamicSharedMemorySize, SMEM_TOTAL);
    score_f16_kernel<<<dim3(MROWS / 128, 2), 256, SMEM_TOTAL>>>(key, W2w, W2b,
                                                                qproj, Vw, score);

    // 3) softmax -> attn
    softmax_kernel<<<BATCH, 256>>>(score, attn);

    // 4) context = attn^T @ value
    context_kernel<<<dim3(BATCH, DIM / 256, 4), 256>>>(attn, value, ctx);
}